// round 2
// baseline (speedup 1.0000x reference)
#include <cuda_runtime.h>

#define BB 4
#define CC 256
#define OO 256
#define HH 96
#define WWD 96
#define PIX (HH*WWD)          // 9216
#define NPIX (BB*PIX)         // 36864
#define KOFF 33

// Scratch (static device globals; no runtime allocation)
__device__ float g_Et[(size_t)NPIX*OO];   // [P, 256] pixel-major
__device__ float g_Ee[(size_t)NPIX*OO];   // [P, 256]
__device__ float g_w [(size_t)NPIX*KOFF]; // [P, 33]

// Star offsets: center, then for s=1..4: a in {-s,0,s} outer, b in {-s,0,s} inner, skip (0,0)
__constant__ int c_offa[KOFF] = {0,
    -1,-1,-1, 0, 0, 1, 1, 1,
    -2,-2,-2, 0, 0, 2, 2, 2,
    -3,-3,-3, 0, 0, 3, 3, 3,
    -4,-4,-4, 0, 0, 4, 4, 4};
__constant__ int c_offb[KOFF] = {0,
    -1, 0, 1,-1, 1,-1, 0, 1,
    -2, 0, 2,-2, 2,-2, 0, 2,
    -3, 0, 3,-3, 3,-3, 0, 3,
    -4, 0, 4,-4, 4,-4, 0, 4};

// ---------------------------------------------------------------------------
// Kernel 1: E[p, o] = sum_c W[o,c] * F[b,c,p] + bias[o]
// Tile: 128 pixels x 128 outs x K-chunk 8. 256 threads, 8x8 micro-tiles.
// blockIdx.z = 0 -> (Ft, Wf, bf) -> g_Et ; z = 1 -> (Fte, Wg, bg) -> g_Ee
// ---------------------------------------------------------------------------
__global__ __launch_bounds__(256, 2)
void gemm_embed(const float* __restrict__ F0, const float* __restrict__ W0, const float* __restrict__ b0,
                const float* __restrict__ F1, const float* __restrict__ W1, const float* __restrict__ b1)
{
    const float* F    = (blockIdx.z == 0) ? F0 : F1;
    const float* Wm   = (blockIdx.z == 0) ? W0 : W1;
    const float* bias = (blockIdx.z == 0) ? b0 : b1;
    float* E          = (blockIdx.z == 0) ? g_Et : g_Ee;

    __shared__ float As[8][128];
    __shared__ float Bs[8][128];

    const int tid = threadIdx.x;
    const int tm  = blockIdx.x;        // 0..287 (72 tiles per batch)
    const int bb  = tm / 72;
    const int p0  = (tm % 72) * 128;
    const int o0  = blockIdx.y * 128;

    const float* Fb = F + (size_t)bb * CC * PIX;

    // A-load mapping: 128 pixels x 8 k, 4 per thread (coalesced along pixels)
    const int tp  = tid & 127;
    const int tk4 = (tid >> 7) * 4;    // 0 or 4
    // B-load mapping: 2 threads per out-row, float4 of k each
    const int to  = tid >> 1;          // 0..127
    const int tc  = (tid & 1) * 4;     // 0 or 4

    const int ty = tid >> 4;           // 0..15
    const int tx = tid & 15;           // 0..15

    float acc[8][8];
    #pragma unroll
    for (int i = 0; i < 8; i++)
        #pragma unroll
        for (int j = 0; j < 8; j++) acc[i][j] = 0.f;

    for (int c0 = 0; c0 < CC; c0 += 8) {
        float a0 = Fb[(size_t)(c0+tk4+0)*PIX + p0 + tp];
        float a1 = Fb[(size_t)(c0+tk4+1)*PIX + p0 + tp];
        float a2 = Fb[(size_t)(c0+tk4+2)*PIX + p0 + tp];
        float a3 = Fb[(size_t)(c0+tk4+3)*PIX + p0 + tp];
        float4 w4 = *(const float4*)&Wm[(size_t)(o0+to)*CC + c0 + tc];

        __syncthreads();
        As[tk4+0][tp] = a0;
        As[tk4+1][tp] = a1;
        As[tk4+2][tp] = a2;
        As[tk4+3][tp] = a3;
        Bs[tc+0][to] = w4.x;
        Bs[tc+1][to] = w4.y;
        Bs[tc+2][to] = w4.z;
        Bs[tc+3][to] = w4.w;
        __syncthreads();

        #pragma unroll
        for (int kk = 0; kk < 8; kk++) {
            float4 av0 = *(const float4*)&As[kk][ty*4];
            float4 av1 = *(const float4*)&As[kk][ty*4 + 64];
            float4 bv0 = *(const float4*)&Bs[kk][tx*4];
            float4 bv1 = *(const float4*)&Bs[kk][tx*4 + 64];
            float a[8] = {av0.x, av0.y, av0.z, av0.w, av1.x, av1.y, av1.z, av1.w};
            float b[8] = {bv0.x, bv0.y, bv0.z, bv0.w, bv1.x, bv1.y, bv1.z, bv1.w};
            #pragma unroll
            for (int i = 0; i < 8; i++)
                #pragma unroll
                for (int j = 0; j < 8; j++)
                    acc[i][j] += a[i] * b[j];
        }
    }

    // Epilogue: add bias, store [P, 256]
    float4 bia0 = *(const float4*)&bias[o0 + tx*4];
    float4 bia1 = *(const float4*)&bias[o0 + tx*4 + 64];
    #pragma unroll
    for (int i = 0; i < 8; i++) {
        int r = (i < 4) ? (ty*4 + i) : (64 + ty*4 + (i-4));
        size_t base = ((size_t)bb*PIX + p0 + r) * OO + o0;
        float4 v0, v1;
        v0.x = acc[i][0] + bia0.x; v0.y = acc[i][1] + bia0.y;
        v0.z = acc[i][2] + bia0.z; v0.w = acc[i][3] + bia0.w;
        v1.x = acc[i][4] + bia1.x; v1.y = acc[i][5] + bia1.y;
        v1.z = acc[i][6] + bia1.z; v1.w = acc[i][7] + bia1.w;
        *(float4*)&E[base + tx*4]      = v0;
        *(float4*)&E[base + tx*4 + 64] = v1;
    }
}

// ---------------------------------------------------------------------------
// Kernel 2: per-pixel 33 affinities + softmax -> g_w [P, 33]
// One warp per pixel; 8 warps per block.
// ---------------------------------------------------------------------------
__global__ __launch_bounds__(256)
void affinity_softmax()
{
    const int warp = threadIdx.x >> 5;
    const int lane = threadIdx.x & 31;
    const int P = blockIdx.x * 8 + warp;
    const int bb = P / PIX;
    const int p  = P % PIX;
    const int x  = p / WWD;
    const int y  = p % WWD;

    const float* ee = g_Ee + (size_t)P * OO;
    float4 e0 = *(const float4*)&ee[lane*8];
    float4 e1 = *(const float4*)&ee[lane*8 + 4];

    __shared__ float s_aff[8][KOFF];
    const float* Etb = g_Et + (size_t)bb * PIX * OO;

    #pragma unroll
    for (int k = 0; k < KOFF; k++) {
        const int a = c_offa[k], b = c_offb[k];
        const int nx = x + a, ny = y + b;
        float aff = -1e30f;
        if (nx >= 0 && nx < HH && ny >= 0 && ny < WWD) {
            const float* et = Etb + (size_t)(nx*WWD + ny) * OO;
            float4 t0 = *(const float4*)&et[lane*8];
            float4 t1 = *(const float4*)&et[lane*8 + 4];
            float d = e0.x*t0.x + e0.y*t0.y + e0.z*t0.z + e0.w*t0.w
                    + e1.x*t1.x + e1.y*t1.y + e1.z*t1.z + e1.w*t1.w;
            #pragma unroll
            for (int s = 16; s > 0; s >>= 1)
                d += __shfl_xor_sync(0xffffffffu, d, s);
            aff = d;
        }
        if (lane == 0) s_aff[warp][k] = aff;
    }
    __syncwarp();

    // Distributed softmax: lane k owns aff[k]; lane 0 also owns aff[32]
    float v0 = s_aff[warp][lane];
    float v1 = (lane == 0) ? s_aff[warp][32] : -1e30f;
    float m = fmaxf(v0, v1);
    #pragma unroll
    for (int s = 16; s > 0; s >>= 1)
        m = fmaxf(m, __shfl_xor_sync(0xffffffffu, m, s));
    float ex0 = (v0 > -1e29f) ? expf(v0 - m) : 0.f;
    float ex1 = (v1 > -1e29f) ? expf(v1 - m) : 0.f;
    float ssum = ex0 + ex1;
    #pragma unroll
    for (int s = 16; s > 0; s >>= 1)
        ssum += __shfl_xor_sync(0xffffffffu, ssum, s);
    float inv = 1.f / ssum;

    float* wrow = g_w + (size_t)P * KOFF;
    wrow[lane] = ex0 * inv;
    if (lane == 0) wrow[32] = ex1 * inv;
}

// ---------------------------------------------------------------------------
// Kernel 3: out[b,c,x,y] = sum_k w[P,k] * Ft[b,c, clamp(x+a_k), clamp(y+b_k)]
// Masked offsets have w == exactly 0 (expf underflow), so clamped loads are safe.
// Block: one (b,x) row x 4 channels; weights staged in smem.
// ---------------------------------------------------------------------------
__global__ __launch_bounds__(384)
void output_gather(const float* __restrict__ Ft, float* __restrict__ out)
{
    const int bx = blockIdx.x;        // 0..383
    const int bb = bx / HH;
    const int x  = bx % HH;
    const int y  = threadIdx.x;       // 0..95
    const int c  = blockIdx.y * 4 + threadIdx.y;

    __shared__ float ws[WWD * KOFF];  // [y][k], contiguous with g_w row block
    const int tid = threadIdx.y * WWD + threadIdx.x;
    const float* wrow = g_w + (size_t)(bb*PIX + x*WWD) * KOFF;
    for (int i = tid; i < WWD * KOFF; i += 384) ws[i] = wrow[i];
    __syncthreads();

    const float* Fb = Ft + ((size_t)bb*CC + c) * PIX;
    float acc = 0.f;
    #pragma unroll
    for (int k = 0; k < KOFF; k++) {
        int nx = x + c_offa[k];
        int ny = y + c_offb[k];
        nx = min(max(nx, 0), HH-1);
        ny = min(max(ny, 0), WWD-1);
        acc += ws[y*KOFF + k] * Fb[nx*WWD + ny];
    }
    out[((size_t)bb*CC + c) * PIX + x*WWD + y] = acc;
}

// ---------------------------------------------------------------------------
extern "C" void kernel_launch(void* const* d_in, const int* in_sizes, int n_in,
                              void* d_out, int out_size)
{
    // Robust pointer binding: big tensors (B*C*H*W), weights (OO*CC), biases (OO),
    // taken in metadata order within each size class.
    const float* big[2]  = {nullptr, nullptr};
    const float* wt[2]   = {nullptr, nullptr};
    const float* bs[2]   = {nullptr, nullptr};
    int nb = 0, nw = 0, nbi = 0;
    for (int i = 0; i < n_in; i++) {
        int sz = in_sizes[i];
        if (sz == BB*CC*PIX)      { if (nb < 2)  big[nb++] = (const float*)d_in[i]; }
        else if (sz == OO*CC)     { if (nw < 2)  wt[nw++]  = (const float*)d_in[i]; }
        else if (sz == OO)        { if (nbi < 2) bs[nbi++] = (const float*)d_in[i]; }
    }
    const float* Ft  = big[0];
    const float* Fte = big[1];
    const float* Wf  = wt[0];
    const float* Wg  = wt[1];
    const float* bf  = bs[0];
    const float* bg  = bs[1];
    float* out = (float*)d_out;

    dim3 g1(288, 2, 2);
    gemm_embed<<<g1, 256>>>(Ft, Wf, bf, Fte, Wg, bg);

    affinity_softmax<<<NPIX/8, 256>>>();

    dim3 g3(BB*HH, OO/4);
    dim3 b3(WWD, 4);
    output_gather<<<g3, b3>>>(Ft, out);
}

// round 3
// speedup vs baseline: 1.0766x; 1.0766x over previous
#include <cuda_runtime.h>

#define BB 4
#define CC 256
#define OO 256
#define HH 96
#define WWD 96
#define PIX (HH*WWD)          // 9216
#define NPIX (BB*PIX)         // 36864
#define KOFF 33

// Scratch (static device globals; no runtime allocation)
__device__ float g_Et[(size_t)NPIX*OO];    // [P, 256] pixel-major
__device__ float g_Ee[(size_t)NPIX*OO];    // [P, 256]
__device__ float g_wT[(size_t)KOFF*NPIX];  // [33, P]  (k-major: coalesced stores/loads)

// ---------------------------------------------------------------------------
// Kernel 1: E[p, o] = sum_c W[o,c] * F[b,c,p] + bias[o]
// Tile: 128 pixels x 128 outs x K-chunk 8. 256 threads, 8x8 micro-tiles.
// ---------------------------------------------------------------------------
__global__ __launch_bounds__(256, 2)
void gemm_embed(const float* __restrict__ F0, const float* __restrict__ W0, const float* __restrict__ b0,
                const float* __restrict__ F1, const float* __restrict__ W1, const float* __restrict__ b1)
{
    const float* F    = (blockIdx.z == 0) ? F0 : F1;
    const float* Wm   = (blockIdx.z == 0) ? W0 : W1;
    const float* bias = (blockIdx.z == 0) ? b0 : b1;
    float* E          = (blockIdx.z == 0) ? g_Et : g_Ee;

    __shared__ float As[8][128];
    __shared__ float Bs[8][128];

    const int tid = threadIdx.x;
    const int tm  = blockIdx.x;
    const int bb  = tm / 72;
    const int p0  = (tm % 72) * 128;
    const int o0  = blockIdx.y * 128;

    const float* Fb = F + (size_t)bb * CC * PIX;

    const int tp  = tid & 127;
    const int tk4 = (tid >> 7) * 4;
    const int to  = tid >> 1;
    const int tc  = (tid & 1) * 4;
    const int ty  = tid >> 4;
    const int tx  = tid & 15;

    float acc[8][8];
    #pragma unroll
    for (int i = 0; i < 8; i++)
        #pragma unroll
        for (int j = 0; j < 8; j++) acc[i][j] = 0.f;

    for (int c0 = 0; c0 < CC; c0 += 8) {
        float a0 = Fb[(size_t)(c0+tk4+0)*PIX + p0 + tp];
        float a1 = Fb[(size_t)(c0+tk4+1)*PIX + p0 + tp];
        float a2 = Fb[(size_t)(c0+tk4+2)*PIX + p0 + tp];
        float a3 = Fb[(size_t)(c0+tk4+3)*PIX + p0 + tp];
        float4 w4 = *(const float4*)&Wm[(size_t)(o0+to)*CC + c0 + tc];

        __syncthreads();
        As[tk4+0][tp] = a0;
        As[tk4+1][tp] = a1;
        As[tk4+2][tp] = a2;
        As[tk4+3][tp] = a3;
        Bs[tc+0][to] = w4.x;
        Bs[tc+1][to] = w4.y;
        Bs[tc+2][to] = w4.z;
        Bs[tc+3][to] = w4.w;
        __syncthreads();

        #pragma unroll
        for (int kk = 0; kk < 8; kk++) {
            float4 av0 = *(const float4*)&As[kk][ty*4];
            float4 av1 = *(const float4*)&As[kk][ty*4 + 64];
            float4 bv0 = *(const float4*)&Bs[kk][tx*4];
            float4 bv1 = *(const float4*)&Bs[kk][tx*4 + 64];
            float a[8] = {av0.x, av0.y, av0.z, av0.w, av1.x, av1.y, av1.z, av1.w};
            float b[8] = {bv0.x, bv0.y, bv0.z, bv0.w, bv1.x, bv1.y, bv1.z, bv1.w};
            #pragma unroll
            for (int i = 0; i < 8; i++)
                #pragma unroll
                for (int j = 0; j < 8; j++)
                    acc[i][j] += a[i] * b[j];
        }
    }

    float4 bia0 = *(const float4*)&bias[o0 + tx*4];
    float4 bia1 = *(const float4*)&bias[o0 + tx*4 + 64];
    #pragma unroll
    for (int i = 0; i < 8; i++) {
        int r = (i < 4) ? (ty*4 + i) : (64 + ty*4 + (i-4));
        size_t base = ((size_t)bb*PIX + p0 + r) * OO + o0;
        float4 v0, v1;
        v0.x = acc[i][0] + bia0.x; v0.y = acc[i][1] + bia0.y;
        v0.z = acc[i][2] + bia0.z; v0.w = acc[i][3] + bia0.w;
        v1.x = acc[i][4] + bia1.x; v1.y = acc[i][5] + bia1.y;
        v1.z = acc[i][6] + bia1.z; v1.w = acc[i][7] + bia1.w;
        *(float4*)&E[base + tx*4]      = v0;
        *(float4*)&E[base + tx*4 + 64] = v1;
    }
}

// ---------------------------------------------------------------------------
// Kernel 2 (rewritten): tiled affinity + softmax.
// Block = 32(y) x 8(x) pixel tile, 256 threads, thread = one pixel.
// Et halo (40y x 16x) staged in smem per 16-channel chunk; Ee read direct to
// regs. 33 accumulators live in registers -> thread-local softmax.
// Halo stages with clamped coords; OOB taps masked to -1e30 before softmax.
// ---------------------------------------------------------------------------
#define TY 32
#define TX 8
#define HY 40          // TY + 8
#define HX 16          // TX + 8
#define CHUNK 16
#define ROWS 41        // padded row stride (floats)
#define PLANE 658      // 16*41 + 2 : channel plane stride, kills STS conflicts

__global__ __launch_bounds__(256)
void affinity_softmax()
{
    const int offa[KOFF] = {0,
        -1,-1,-1, 0, 0, 1, 1, 1,  -2,-2,-2, 0, 0, 2, 2, 2,
        -3,-3,-3, 0, 0, 3, 3, 3,  -4,-4,-4, 0, 0, 4, 4, 4};
    const int offb[KOFF] = {0,
        -1, 0, 1,-1, 1,-1, 0, 1,  -2, 0, 2,-2, 2,-2, 0, 2,
        -3, 0, 3,-3, 3,-3, 0, 3,  -4, 0, 4,-4, 4,-4, 0, 4};

    __shared__ float sEt[CHUNK * PLANE];   // [c][hx][hy] padded

    const int tid  = threadIdx.x;
    const int lane = tid & 31;             // y within tile
    const int txl  = tid >> 5;             // x within tile (0..7)

    const int y0 = blockIdx.x * TY;
    const int x0 = blockIdx.y * TX;
    const int bb = blockIdx.z;

    const int x = x0 + txl;
    const int y = y0 + lane;
    const int P = bb*PIX + x*WWD + y;

    const float* EeP = g_Ee + (size_t)P * OO;
    const float* Etb = g_Et + (size_t)bb * PIX * OO;

    float acc[KOFF];
    #pragma unroll
    for (int k = 0; k < KOFF; k++) acc[k] = 0.f;

    for (int c0 = 0; c0 < CC; c0 += CHUNK) {
        __syncthreads();
        // Stage Et halo chunk: 640 px x 16 ch. idx = px*4 + cg (cg = 4-ch group)
        #pragma unroll
        for (int it = 0; it < 10; it++) {
            int idx  = it * 256 + tid;          // 0..2559
            int pxi  = idx >> 2;                // 0..639
            int cg   = idx & 3;
            int hx   = pxi / HY;
            int hy   = pxi % HY;
            int gx   = x0 - 4 + hx;  gx = min(max(gx, 0), HH-1);
            int gy   = y0 - 4 + hy;  gy = min(max(gy, 0), WWD-1);
            float4 v = *(const float4*)&Etb[(size_t)(gx*WWD + gy) * OO + c0 + cg*4];
            int sbase = (cg*4) * PLANE + hx * ROWS + hy;
            sEt[sbase            ] = v.x;
            sEt[sbase +     PLANE] = v.y;
            sEt[sbase + 2 * PLANE] = v.z;
            sEt[sbase + 3 * PLANE] = v.w;
        }
        __syncthreads();

        // Own Ee chunk -> regs
        float e[CHUNK];
        #pragma unroll
        for (int q = 0; q < CHUNK/4; q++) {
            float4 v = *(const float4*)&EeP[c0 + q*4];
            e[q*4+0] = v.x; e[q*4+1] = v.y; e[q*4+2] = v.z; e[q*4+3] = v.w;
        }

        // Accumulate 33 taps
        #pragma unroll
        for (int c = 0; c < CHUNK; c++) {
            const float ec = e[c];
            const float* sp = &sEt[c * PLANE + (txl + 4) * ROWS + (lane + 4)];
            #pragma unroll
            for (int k = 0; k < KOFF; k++)
                acc[k] += ec * sp[offa[k] * ROWS + offb[k]];
        }
    }

    // Mask invalid taps, softmax (thread-local)
    float m = -1e30f;
    #pragma unroll
    for (int k = 0; k < KOFF; k++) {
        int nx = x + offa[k], ny = y + offb[k];
        if (nx < 0 || nx >= HH || ny < 0 || ny >= WWD) acc[k] = -1e30f;
        m = fmaxf(m, acc[k]);
    }
    float ssum = 0.f;
    #pragma unroll
    for (int k = 0; k < KOFF; k++) {
        acc[k] = expf(acc[k] - m);   // masked -> exp(-huge) = 0
        ssum += acc[k];
    }
    float inv = 1.f / ssum;
    #pragma unroll
    for (int k = 0; k < KOFF; k++)
        g_wT[(size_t)k * NPIX + P] = acc[k] * inv;   // coalesced per k
}

// ---------------------------------------------------------------------------
// Kernel 3: out[b,c,x,y] = sum_k w[k,P] * Ft[b,c, clamp(x+a), clamp(y+b)]
// Block: one (b,x) row x 8 channels (768 thr); weights staged once in smem.
// Masked taps have w == exactly 0, so clamped loads are safe.
// ---------------------------------------------------------------------------
__global__ __launch_bounds__(768)
void output_gather(const float* __restrict__ Ft, float* __restrict__ out)
{
    const int offa[KOFF] = {0,
        -1,-1,-1, 0, 0, 1, 1, 1,  -2,-2,-2, 0, 0, 2, 2, 2,
        -3,-3,-3, 0, 0, 3, 3, 3,  -4,-4,-4, 0, 0, 4, 4, 4};
    const int offb[KOFF] = {0,
        -1, 0, 1,-1, 1,-1, 0, 1,  -2, 0, 2,-2, 2,-2, 0, 2,
        -3, 0, 3,-3, 3,-3, 0, 3,  -4, 0, 4,-4, 4,-4, 0, 4};

    const int bx = blockIdx.x;        // 0..383
    const int bb = bx / HH;
    const int x  = bx % HH;
    const int y  = threadIdx.x;       // 0..95
    const int c  = blockIdx.y * 8 + threadIdx.y;

    __shared__ float ws[KOFF][WWD];
    const int tid = threadIdx.y * WWD + threadIdx.x;
    const int rowbase = bb*PIX + x*WWD;
    for (int i = tid; i < KOFF*WWD; i += 768) {
        int k = i / WWD, yy = i % WWD;
        ws[k][yy] = g_wT[(size_t)k * NPIX + rowbase + yy];
    }
    __syncthreads();

    const float* Fb = Ft + ((size_t)bb*CC + c) * PIX;
    float accv = 0.f;
    #pragma unroll
    for (int k = 0; k < KOFF; k++) {
        int nx = x + offa[k];
        int ny = y + offb[k];
        nx = min(max(nx, 0), HH-1);
        ny = min(max(ny, 0), WWD-1);
        accv += ws[k][y] * Fb[nx*WWD + ny];
    }
    out[((size_t)bb*CC + c) * PIX + x*WWD + y] = accv;
}

// ---------------------------------------------------------------------------
extern "C" void kernel_launch(void* const* d_in, const int* in_sizes, int n_in,
                              void* d_out, int out_size)
{
    const float* big[2]  = {nullptr, nullptr};
    const float* wt[2]   = {nullptr, nullptr};
    const float* bs[2]   = {nullptr, nullptr};
    int nb = 0, nw = 0, nbi = 0;
    for (int i = 0; i < n_in; i++) {
        int sz = in_sizes[i];
        if (sz == BB*CC*PIX)      { if (nb < 2)  big[nb++] = (const float*)d_in[i]; }
        else if (sz == OO*CC)     { if (nw < 2)  wt[nw++]  = (const float*)d_in[i]; }
        else if (sz == OO)        { if (nbi < 2) bs[nbi++] = (const float*)d_in[i]; }
    }
    const float* Ft  = big[0];
    const float* Fte = big[1];
    const float* Wf  = wt[0];
    const float* Wg  = wt[1];
    const float* bf  = bs[0];
    const float* bg  = bs[1];
    float* out = (float*)d_out;

    dim3 g1(288, 2, 2);
    gemm_embed<<<g1, 256>>>(Ft, Wf, bf, Fte, Wg, bg);

    dim3 g2(HH/TY, WWD/TX, BB);      // (3, 12, 4)
    affinity_softmax<<<g2, 256>>>();

    dim3 g3(BB*HH, OO/8);
    dim3 b3(WWD, 8);
    output_gather<<<g3, b3>>>(Ft, out);
}

// round 5
// speedup vs baseline: 1.2549x; 1.1656x over previous
#include <cuda_runtime.h>
#include <cuda_bf16.h>
#include <cstdint>

#define BB 4
#define CC 256
#define OO 256
#define HH 96
#define WWD 96
#define PIX (HH*WWD)          // 9216
#define NPIX (BB*PIX)         // 36864
#define KOFF 33

// ---------------- static device scratch ----------------
__device__ float g_Et[(size_t)NPIX*OO];    // [P, 256]
__device__ float g_Ee[(size_t)NPIX*OO];    // [P, 256]
__device__ float g_wT[(size_t)KOFF*NPIX];  // [33, P]
__device__ __nv_bfloat16 g_AThi[2][(size_t)NPIX*CC];  // F transposed [P, C], hi
__device__ __nv_bfloat16 g_ATlo[2][(size_t)NPIX*CC];  // lo
__device__ __nv_bfloat16 g_Whi[2][OO*CC];             // W [O, C] hi
__device__ __nv_bfloat16 g_Wlo[2][OO*CC];             // lo

// ---------------- helpers ----------------
__device__ __forceinline__ uint32_t smem_u32(const void* p) {
    uint32_t a;
    asm("{ .reg .u64 t; cvta.to.shared.u64 t, %1; cvt.u32.u64 %0, t; }" : "=r"(a) : "l"(p));
    return a;
}
__device__ __forceinline__ void cp16(uint32_t dst, const void* src) {
    asm volatile("cp.async.cg.shared.global [%0], [%1], 16;" :: "r"(dst), "l"(src));
}
__device__ __forceinline__ void ldmx4(uint32_t* r, uint32_t addr) {
    asm volatile("ldmatrix.sync.aligned.m8n8.x4.shared.b16 {%0,%1,%2,%3}, [%4];"
        : "=r"(r[0]), "=r"(r[1]), "=r"(r[2]), "=r"(r[3]) : "r"(addr));
}
__device__ __forceinline__ void mma_bf16(float* d, const uint32_t* a, uint32_t b0, uint32_t b1) {
    asm volatile(
        "mma.sync.aligned.m16n8k16.row.col.f32.bf16.bf16.f32 "
        "{%0,%1,%2,%3}, {%4,%5,%6,%7}, {%8,%9}, {%0,%1,%2,%3};"
        : "+f"(d[0]), "+f"(d[1]), "+f"(d[2]), "+f"(d[3])
        : "r"(a[0]), "r"(a[1]), "r"(a[2]), "r"(a[3]), "r"(b0), "r"(b1));
}

// ---------------------------------------------------------------------------
// Pre-kernel A: W fp32 -> (hi, lo) bf16, same [O, C] layout (K-major)
// ---------------------------------------------------------------------------
__global__ void convert_w(const float* __restrict__ W0, const float* __restrict__ W1)
{
    int t = blockIdx.y;
    const float* W = t ? W1 : W0;
    for (int i = blockIdx.x * 256 + threadIdx.x; i < OO*CC; i += gridDim.x * 256) {
        float v = W[i];
        __nv_bfloat16 hi = __float2bfloat16(v);
        g_Whi[t][i] = hi;
        g_Wlo[t][i] = __float2bfloat16(v - __bfloat162float(hi));
    }
}

// ---------------------------------------------------------------------------
// Pre-kernel B: transpose F [b,c,p] -> [bP+p, c] and split into hi/lo bf16
// ---------------------------------------------------------------------------
__global__ __launch_bounds__(256)
void transpose_convert(const float* __restrict__ F0, const float* __restrict__ F1)
{
    __shared__ float tile[32][33];
    const int p0 = blockIdx.x * 32;
    const int c0 = blockIdx.y * 32;
    const int z  = blockIdx.z;          // b*2 + t
    const int bb = z >> 1, t = z & 1;
    const float* src = (t == 0 ? F0 : F1) + (size_t)bb * CC * PIX;
    const int tx = threadIdx.x, ty = threadIdx.y;   // (32, 8)

    #pragma unroll
    for (int i = 0; i < 4; i++) {
        int c = c0 + ty + i*8;
        tile[ty + i*8][tx] = src[(size_t)c * PIX + p0 + tx];
    }
    __syncthreads();

    __nv_bfloat16* dhi = g_AThi[t];
    __nv_bfloat16* dlo = g_ATlo[t];
    #pragma unroll
    for (int i = 0; i < 4; i++) {
        int p = p0 + ty + i*8;
        float v = tile[tx][ty + i*8];
        __nv_bfloat16 hi = __float2bfloat16(v);
        __nv_bfloat16 lo = __float2bfloat16(v - __bfloat162float(hi));
        size_t idx = ((size_t)(bb*PIX + p)) * CC + c0 + tx;
        dhi[idx] = hi;
        dlo[idx] = lo;
    }
}

// ---------------------------------------------------------------------------
// bf16 mma.sync GEMM: E[p, o] = sum_c A[p,c]*W[o,c] (3-product hi/lo split)
// CTA: 128 pixels x 128 outs. 8 warps (warp_m 0..3 x warp_n 0..1), warp tile
// 32(m) x 64(n). K chunks of 32 (2 k-steps), cp.async double-buffered.
// smem rows padded to 80B (20 words): ldmatrix 8-row phases conflict-free.
// ---------------------------------------------------------------------------
#define LDROW 80               // bytes per smem row (64 data + 16 pad)
#define OP_SZ (128*LDROW)      // 10240 bytes per operand tile
#define TSTAGE (4*OP_SZ)       // A_h, A_l, B_h, B_l
#define SM_GEMM_TOTAL (2*TSTAGE)  // 81920
#define NCH 8                  // 256 / 32

__global__ __launch_bounds__(256)
void gemm_mma(const float* __restrict__ bias0, const float* __restrict__ bias1)
{
    extern __shared__ char smem[];
    const uint32_t sbase = smem_u32(smem);
    const int tid  = threadIdx.x;
    const int wid  = tid >> 5;
    const int lane = tid & 31;
    const int warp_m = wid & 3;        // 0..3 -> m offset *32
    const int warp_n = wid >> 2;       // 0..1 -> n offset *64

    const int p0 = blockIdx.x * 128;
    const int o0 = blockIdx.y * 128;
    const int t  = blockIdx.z;

    const __nv_bfloat16* Ahi = g_AThi[t];
    const __nv_bfloat16* Alo = g_ATlo[t];
    const __nv_bfloat16* Bhi = g_Whi[t];
    const __nv_bfloat16* Blo = g_Wlo[t];
    const float* bias = (t == 0) ? bias0 : bias1;
    float* E          = (t == 0) ? g_Et  : g_Ee;

    float acc[2][8][4];
    #pragma unroll
    for (int i = 0; i < 2; i++)
        #pragma unroll
        for (int j = 0; j < 8; j++)
            #pragma unroll
            for (int q = 0; q < 4; q++) acc[i][j][q] = 0.f;

    // staging lambda (manual): 8 cp.async per thread per stage
    const int srow = tid >> 2;          // 0..63  (x2 via +64)
    const int sun  = tid & 3;           // 16B unit 0..3

    auto stage = [&](int buf, int c0) {
        uint32_t s = sbase + buf * TSTAGE;
        #pragma unroll
        for (int j = 0; j < 2; j++) {
            int row = srow + j * 64;
            uint32_t soff = row * LDROW + sun * 16;
            const __nv_bfloat16* gA = Ahi + (size_t)(p0 + row) * CC + c0 + sun * 8;
            const __nv_bfloat16* gAl= Alo + (size_t)(p0 + row) * CC + c0 + sun * 8;
            const __nv_bfloat16* gB = Bhi + (size_t)(o0 + row) * CC + c0 + sun * 8;
            const __nv_bfloat16* gBl= Blo + (size_t)(o0 + row) * CC + c0 + sun * 8;
            cp16(s +          soff, gA);
            cp16(s + OP_SZ  + soff, gAl);
            cp16(s + 2*OP_SZ+ soff, gB);
            cp16(s + 3*OP_SZ+ soff, gBl);
        }
        asm volatile("cp.async.commit_group;");
    };

    stage(0, 0);

    // ldmatrix base offsets (within operand tile), per k-step add ks*32
    const uint32_t aoff = (uint32_t)((warp_m*32 + (lane & 15)) * LDROW + (lane >> 4) * 16);
    const uint32_t boff = (uint32_t)((warp_n*64 + ((lane >> 4) << 3) + (lane & 7)) * LDROW
                                     + ((lane >> 3) & 1) * 16);

    for (int c = 0; c < NCH; c++) {
        if (c + 1 < NCH) {
            stage((c + 1) & 1, (c + 1) * 32);
            asm volatile("cp.async.wait_group 1;");
        } else {
            asm volatile("cp.async.wait_group 0;");
        }
        __syncthreads();

        uint32_t sA = sbase + (c & 1) * TSTAGE;
        uint32_t sB = sA + 2 * OP_SZ;

        #pragma unroll
        for (int ks = 0; ks < 2; ks++) {
            uint32_t a_h[2][4], a_l[2][4];
            #pragma unroll
            for (int mt = 0; mt < 2; mt++) {
                uint32_t addr = sA + aoff + mt * (16 * LDROW) + ks * 32;
                ldmx4(a_h[mt], addr);
                ldmx4(a_l[mt], addr + OP_SZ);
            }
            #pragma unroll
            for (int nt2 = 0; nt2 < 4; nt2++) {
                uint32_t baddr = sB + boff + nt2 * (16 * LDROW) + ks * 32;
                uint32_t bh[4], bl[4];
                ldmx4(bh, baddr);
                ldmx4(bl, baddr + OP_SZ);
                #pragma unroll
                for (int half = 0; half < 2; half++) {
                    uint32_t bh0 = bh[half*2], bh1 = bh[half*2+1];
                    uint32_t bl0 = bl[half*2], bl1 = bl[half*2+1];
                    int nt = nt2*2 + half;
                    #pragma unroll
                    for (int mt = 0; mt < 2; mt++) {
                        mma_bf16(acc[mt][nt], a_h[mt], bh0, bh1);
                        mma_bf16(acc[mt][nt], a_h[mt], bl0, bl1);
                        mma_bf16(acc[mt][nt], a_l[mt], bh0, bh1);
                    }
                }
            }
        }
        __syncthreads();
    }

    // epilogue: d0,d1 -> (m, n..n+1); d2,d3 -> (m+8, n..n+1)
    const int m_base = p0 + warp_m * 32 + (lane >> 2);
    const int n_base = o0 + warp_n * 64 + (lane & 3) * 2;
    #pragma unroll
    for (int mt = 0; mt < 2; mt++) {
        #pragma unroll
        for (int nt = 0; nt < 8; nt++) {
            int m = m_base + mt * 16;
            int n = n_base + nt * 8;
            float b0 = bias[n], b1 = bias[n + 1];
            float2 v0 = make_float2(acc[mt][nt][0] + b0, acc[mt][nt][1] + b1);
            float2 v1 = make_float2(acc[mt][nt][2] + b0, acc[mt][nt][3] + b1);
            *(float2*)&E[(size_t)m * OO + n]       = v0;
            *(float2*)&E[(size_t)(m + 8) * OO + n] = v1;
        }
    }
}

// ---------------------------------------------------------------------------
// Kernel 2: tiled affinity + softmax (unchanged from R3)
// ---------------------------------------------------------------------------
#define TY 32
#define TX 8
#define HY 40
#define HX 16
#define CHUNK 16
#define ROWS 41
#define PLANE 658

__global__ __launch_bounds__(256)
void affinity_softmax()
{
    const int offa[KOFF] = {0,
        -1,-1,-1, 0, 0, 1, 1, 1,  -2,-2,-2, 0, 0, 2, 2, 2,
        -3,-3,-3, 0, 0, 3, 3, 3,  -4,-4,-4, 0, 0, 4, 4, 4};
    const int offb[KOFF] = {0,
        -1, 0, 1,-1, 1,-1, 0, 1,  -2, 0, 2,-2, 2,-2, 0, 2,
        -3, 0, 3,-3, 3,-3, 0, 3,  -4, 0, 4,-4, 4,-4, 0, 4};

    __shared__ float sEt[CHUNK * PLANE];

    const int tid  = threadIdx.x;
    const int lane = tid & 31;
    const int txl  = tid >> 5;

    const int y0 = blockIdx.x * TY;
    const int x0 = blockIdx.y * TX;
    const int bb = blockIdx.z;

    const int x = x0 + txl;
    const int y = y0 + lane;
    const int P = bb*PIX + x*WWD + y;

    const float* EeP = g_Ee + (size_t)P * OO;
    const float* Etb = g_Et + (size_t)bb * PIX * OO;

    float acc[KOFF];
    #pragma unroll
    for (int k = 0; k < KOFF; k++) acc[k] = 0.f;

    for (int c0 = 0; c0 < CC; c0 += CHUNK) {
        __syncthreads();
        #pragma unroll
        for (int it = 0; it < 10; it++) {
            int idx  = it * 256 + tid;
            int pxi  = idx >> 2;
            int cg   = idx & 3;
            int hx   = pxi / HY;
            int hy   = pxi % HY;
            int gx   = x0 - 4 + hx;  gx = min(max(gx, 0), HH-1);
            int gy   = y0 - 4 + hy;  gy = min(max(gy, 0), WWD-1);
            float4 v = *(const float4*)&Etb[(size_t)(gx*WWD + gy) * OO + c0 + cg*4];
            int sb2 = (cg*4) * PLANE + hx * ROWS + hy;
            sEt[sb2            ] = v.x;
            sEt[sb2 +     PLANE] = v.y;
            sEt[sb2 + 2 * PLANE] = v.z;
            sEt[sb2 + 3 * PLANE] = v.w;
        }
        __syncthreads();

        float e[CHUNK];
        #pragma unroll
        for (int q = 0; q < CHUNK/4; q++) {
            float4 v = *(const float4*)&EeP[c0 + q*4];
            e[q*4+0] = v.x; e[q*4+1] = v.y; e[q*4+2] = v.z; e[q*4+3] = v.w;
        }

        #pragma unroll
        for (int cc2 = 0; cc2 < CHUNK; cc2++) {
            const float ec = e[cc2];
            const float* sp = &sEt[cc2 * PLANE + (txl + 4) * ROWS + (lane + 4)];
            #pragma unroll
            for (int k = 0; k < KOFF; k++)
                acc[k] += ec * sp[offa[k] * ROWS + offb[k]];
        }
    }

    float m = -1e30f;
    #pragma unroll
    for (int k = 0; k < KOFF; k++) {
        int nx = x + offa[k], ny = y + offb[k];
        if (nx < 0 || nx >= HH || ny < 0 || ny >= WWD) acc[k] = -1e30f;
        m = fmaxf(m, acc[k]);
    }
    float ssum = 0.f;
    #pragma unroll
    for (int k = 0; k < KOFF; k++) {
        acc[k] = expf(acc[k] - m);
        ssum += acc[k];
    }
    float inv = 1.f / ssum;
    #pragma unroll
    for (int k = 0; k < KOFF; k++)
        g_wT[(size_t)k * NPIX + P] = acc[k] * inv;
}

// ---------------------------------------------------------------------------
// Kernel 3: output gather (unchanged from R3)
// ---------------------------------------------------------------------------
__global__ __launch_bounds__(768)
void output_gather(const float* __restrict__ Ft, float* __restrict__ out)
{
    const int offa[KOFF] = {0,
        -1,-1,-1, 0, 0, 1, 1, 1,  -2,-2,-2, 0, 0, 2, 2, 2,
        -3,-3,-3, 0, 0, 3, 3, 3,  -4,-4,-4, 0, 0, 4, 4, 4};
    const int offb[KOFF] = {0,
        -1, 0, 1,-1, 1,-1, 0, 1,  -2, 0, 2,-2, 2,-2, 0, 2,
        -3, 0, 3,-3, 3,-3, 0, 3,  -4, 0, 4,-4, 4,-4, 0, 4};

    const int bx = blockIdx.x;
    const int bb = bx / HH;
    const int x  = bx % HH;
    const int y  = threadIdx.x;
    const int c  = blockIdx.y * 8 + threadIdx.y;

    __shared__ float ws[KOFF][WWD];
    const int tid = threadIdx.y * WWD + threadIdx.x;
    const int rowbase = bb*PIX + x*WWD;
    for (int i = tid; i < KOFF*WWD; i += 768) {
        int k = i / WWD, yy = i % WWD;
        ws[k][yy] = g_wT[(size_t)k * NPIX + rowbase + yy];
    }
    __syncthreads();

    const float* Fb = Ft + ((size_t)bb*CC + c) * PIX;
    float accv = 0.f;
    #pragma unroll
    for (int k = 0; k < KOFF; k++) {
        int nx = x + offa[k];
        int ny = y + offb[k];
        nx = min(max(nx, 0), HH-1);
        ny = min(max(ny, 0), WWD-1);
        accv += ws[k][y] * Fb[nx*WWD + ny];
    }
    out[((size_t)bb*CC + c) * PIX + x*WWD + y] = accv;
}

// ---------------------------------------------------------------------------
extern "C" void kernel_launch(void* const* d_in, const int* in_sizes, int n_in,
                              void* d_out, int out_size)
{
    const float* big[2]  = {nullptr, nullptr};
    const float* wt[2]   = {nullptr, nullptr};
    const float* bs[2]   = {nullptr, nullptr};
    int nb = 0, nw = 0, nbi = 0;
    for (int i = 0; i < n_in; i++) {
        int sz = in_sizes[i];
        if (sz == BB*CC*PIX)      { if (nb < 2)  big[nb++] = (const float*)d_in[i]; }
        else if (sz == OO*CC)     { if (nw < 2)  wt[nw++]  = (const float*)d_in[i]; }
        else if (sz == OO)        { if (nbi < 2) bs[nbi++] = (const float*)d_in[i]; }
    }
    const float* Ft  = big[0];
    const float* Fte = big[1];
    const float* Wf  = wt[0];
    const float* Wg  = wt[1];
    const float* bf  = bs[0];
    const float* bg  = bs[1];
    float* out = (float*)d_out;

    cudaFuncSetAttribute(gemm_mma, cudaFuncAttributeMaxDynamicSharedMemorySize, SM_GEMM_TOTAL);

    convert_w<<<dim3(32, 2), 256>>>(Wf, Wg);
    transpose_convert<<<dim3(PIX/32, CC/32, BB*2), dim3(32, 8)>>>(Ft, Fte);
    gemm_mma<<<dim3(NPIX/128, 2, 2), 256, SM_GEMM_TOTAL>>>(bf, bg);

    dim3 g2(HH/TY, WWD/TX, BB);
    affinity_softmax<<<g2, 256>>>();

    dim3 g3(BB*HH, OO/8);
    dim3 b3(WWD, 8);
    output_gather<<<g3, b3>>>(Ft, out);
}